// round 2
// baseline (speedup 1.0000x reference)
#include <cuda_runtime.h>
#include <math.h>

// ---------------- Problem constants ----------------
#define B_ROWS   1024
#define OBS_DIM  512
#define ACT_DIM  64
#define KD       128
#define CAP      131072

// ---------------- Phase B tiling ----------------
#define KSPLIT   64
#define KEYS_PER_SPLIT (CAP / KSPLIT)        // 2048
#define NTILE    64
#define NTILES   (KEYS_PER_SPLIT / NTILE)    // 32
#define MTILE    64
#define PAD      132                         // floats per smem row (bank-stagger + 16B align)

// Scratch (no cudaMalloc allowed)
__device__ float g_H [B_ROWS * KD];
__device__ float g_pm[B_ROWS * KSPLIT];
__device__ float g_pl[B_ROWS * KSPLIT];
__device__ float g_pa[B_ROWS * KSPLIT];

// ---------------- Helpers ----------------
__device__ __forceinline__ float ex2(float x) {
    float r;
    asm("ex2.approx.ftz.f32 %0, %1;" : "=f"(r) : "f"(x));
    return r;
}

// Packed fp32x2 FMA (Blackwell FFMA2) — 2x fp32 throughput vs 3-reg FFMA.
__device__ __forceinline__ void ffma2(unsigned long long &d,
                                      unsigned long long a,
                                      unsigned long long b) {
    asm("fma.rn.f32x2 %0, %1, %2, %0;" : "+l"(d) : "l"(a), "l"(b));
}

__device__ __forceinline__ unsigned smem_u32(const void* p) {
    return (unsigned)__cvta_generic_to_shared(p);
}
__device__ __forceinline__ void cp_async16(unsigned dst, const void* src) {
    asm volatile("cp.async.cg.shared.global [%0], [%1], 16;" :: "r"(dst), "l"(src) : "memory");
}
__device__ __forceinline__ void cp_commit() {
    asm volatile("cp.async.commit_group;" ::: "memory");
}

// =====================================================================
// Phase A: fused MLP.  8 batch rows per block, 256 threads.
//   inpt = L2norm(obs @ pred_W^T + pred_b)
//   h1   = relu([inpt, action] @ t1_W^T + t1_b)
//   H    = h1 @ t2_W^T + t2_b          -> g_H (1024 x 128)
// =====================================================================
__global__ void __launch_bounds__(256)
phaseA_kernel(const float* __restrict__ obs,   const float* __restrict__ action,
              const float* __restrict__ pW,    const float* __restrict__ pb,
              const float* __restrict__ t1W,   const float* __restrict__ t1b,
              const float* __restrict__ t2W,   const float* __restrict__ t2b)
{
    __shared__ float s_obs[8 * 516];   // padded rows (516*4 % 16 == 0)
    __shared__ float s_in [8 * 196];   // concat(inpt_norm[128], action[64]) padded
    __shared__ float s_h1 [8 * 132];
    __shared__ float s_rn [8];

    const int tid = threadIdx.x;
    const int rb  = blockIdx.x * 8;

    // Load obs rows (coalesced float4). 8 rows * 128 float4 = 1024 items.
    #pragma unroll
    for (int j = 0; j < 4; j++) {
        int g  = j * 256 + tid;    // 0..1023
        int r  = g >> 7;           // 0..7
        int k4 = g & 127;          // 0..127 float4s
        float4 v = ((const float4*)obs)[(rb + r) * 128 + k4];
        *(float4*)&s_obs[r * 516 + k4 * 4] = v;
    }
    // Load action into s_in cols [128,192)
    #pragma unroll
    for (int j = 0; j < 2; j++) {
        int g = j * 256 + tid;
        int r = g >> 6, a = g & 63;
        s_in[r * 196 + 128 + a] = action[(rb + r) * 64 + a];
    }
    __syncthreads();

    const int jj = tid & 127;      // output feature
    const int rg = tid >> 7;       // row group (0 or 1), 4 rows each

    // ---- predictor: inpt[r][jj] = dot(obs_r, pW[jj], 512) + pb[jj]
    float acc0[4] = {0.f, 0.f, 0.f, 0.f};
    {
        const float4* wp = (const float4*)pW + jj * 128;
        #pragma unroll 4
        for (int k = 0; k < 512; k += 4) {
            float4 w = __ldg(wp + (k >> 2));
            #pragma unroll
            for (int i = 0; i < 4; i++) {
                float4 o = *(const float4*)&s_obs[(rg * 4 + i) * 516 + k];
                acc0[i] = fmaf(w.x, o.x, acc0[i]);
                acc0[i] = fmaf(w.y, o.y, acc0[i]);
                acc0[i] = fmaf(w.z, o.z, acc0[i]);
                acc0[i] = fmaf(w.w, o.w, acc0[i]);
            }
        }
    }
    float bias0 = pb[jj];
    float raw[4];
    #pragma unroll
    for (int i = 0; i < 4; i++) {
        raw[i] = acc0[i] + bias0;
        s_in[(rg * 4 + i) * 196 + jj] = raw[i];
    }
    __syncthreads();

    // ---- row L2 norms (warp w handles row w)
    {
        int w = tid >> 5, lane = tid & 31;
        float ss = 0.f;
        #pragma unroll
        for (int c = lane; c < 128; c += 32) {
            float x = s_in[w * 196 + c];
            ss = fmaf(x, x, ss);
        }
        #pragma unroll
        for (int d = 16; d > 0; d >>= 1) ss += __shfl_xor_sync(0xffffffffu, ss, d);
        if (lane == 0) s_rn[w] = 1.0f / fmaxf(sqrtf(ss), 1e-12f);
    }
    __syncthreads();
    #pragma unroll
    for (int i = 0; i < 4; i++)
        s_in[(rg * 4 + i) * 196 + jj] = raw[i] * s_rn[rg * 4 + i];
    __syncthreads();

    // ---- layer 1: h1 = relu(s_in @ t1W^T + t1b)   (192 -> 128)
    float acc1[4] = {0.f, 0.f, 0.f, 0.f};
    {
        const float4* wp = (const float4*)t1W + jj * 48;
        #pragma unroll 4
        for (int k = 0; k < 192; k += 4) {
            float4 w = __ldg(wp + (k >> 2));
            #pragma unroll
            for (int i = 0; i < 4; i++) {
                float4 o = *(const float4*)&s_in[(rg * 4 + i) * 196 + k];
                acc1[i] = fmaf(w.x, o.x, acc1[i]);
                acc1[i] = fmaf(w.y, o.y, acc1[i]);
                acc1[i] = fmaf(w.z, o.z, acc1[i]);
                acc1[i] = fmaf(w.w, o.w, acc1[i]);
            }
        }
    }
    float bias1 = t1b[jj];
    #pragma unroll
    for (int i = 0; i < 4; i++)
        s_h1[(rg * 4 + i) * 132 + jj] = fmaxf(acc1[i] + bias1, 0.0f);
    __syncthreads();

    // ---- layer 2: H = s_h1 @ t2W^T + t2b   (128 -> 128)
    float acc2[4] = {0.f, 0.f, 0.f, 0.f};
    {
        const float4* wp = (const float4*)t2W + jj * 32;
        #pragma unroll 4
        for (int k = 0; k < 128; k += 4) {
            float4 w = __ldg(wp + (k >> 2));
            #pragma unroll
            for (int i = 0; i < 4; i++) {
                float4 o = *(const float4*)&s_h1[(rg * 4 + i) * 132 + k];
                acc2[i] = fmaf(w.x, o.x, acc2[i]);
                acc2[i] = fmaf(w.y, o.y, acc2[i]);
                acc2[i] = fmaf(w.z, o.z, acc2[i]);
                acc2[i] = fmaf(w.w, o.w, acc2[i]);
            }
        }
    }
    float bias2 = t2b[jj];
    #pragma unroll
    for (int i = 0; i < 4; i++)
        g_H[(rb + rg * 4 + i) * 128 + jj] = acc2[i] + bias2;
}

// =====================================================================
// Phase B: fused scores GEMM + online softmax + value readout (split-K).
// Grid (KSPLIT, 16 row-tiles). 256 threads; 4x4 microtile per thread;
// f32x2-packed K-dim accumulation; cp.async double-buffered key tiles.
// Per-thread online softmax state; cross-thread LSE merge at the end.
// =====================================================================
__global__ void __launch_bounds__(256, 2)
phaseB_kernel(const float* __restrict__ keys, const float* __restrict__ values,
              const float* __restrict__ log_temp)
{
    extern __shared__ float sm[];
    float* s_h = sm;                          // MTILE * PAD
    float* s_k = sm + MTILE * PAD;            // 2 * NTILE * PAD
    float* s_v = s_k + 2 * NTILE * PAD;       // 2 * NTILE

    const int tid = threadIdx.x;
    const int bx  = blockIdx.x;               // key split
    const int rb  = blockIdx.y * MTILE;       // row base
    const int key0 = bx * KEYS_PER_SPLIT;

    const float L2E = 1.4426950408889634f;
    const float lt  = *log_temp;
    const float scale2 = ex2(-lt * L2E) * L2E;   // (1/T) * log2(e)

    // ---- issue key tiles 0 and 1 via cp.async ----
    #pragma unroll
    for (int t = 0; t < 2; t++) {
        #pragma unroll
        for (int j = 0; j < 8; j++) {
            int g  = j * 256 + tid;
            int n  = g >> 5;       // key within tile
            int k4 = g & 31;       // float4 within row
            cp_async16(smem_u32(&s_k[(t & 1) * NTILE * PAD + n * PAD + k4 * 4]),
                       keys + (size_t)(key0 + t * NTILE + n) * 128 + k4 * 4);
        }
        if (tid < 16)
            cp_async16(smem_u32(&s_v[(t & 1) * NTILE + tid * 4]),
                       values + key0 + t * NTILE + tid * 4);
        cp_commit();
    }

    // ---- load h tile (plain, covered by first sync) ----
    #pragma unroll
    for (int j = 0; j < 8; j++) {
        int g  = j * 256 + tid;
        int m  = g >> 5;
        int k4 = g & 31;
        float4 v = ((const float4*)g_H)[(rb + m) * 32 + k4];
        *(float4*)&s_h[m * PAD + k4 * 4] = v;
    }

    const int mt = tid >> 4;     // 0..15, rows mt + 16*i
    const int nt = tid & 15;     // 0..15, keys nt + 16*j (strided -> low LDS conflicts)

    float rmax[4], rl[4], ra[4];
    #pragma unroll
    for (int i = 0; i < 4; i++) { rmax[i] = -1e30f; rl[i] = 0.f; ra[i] = 0.f; }

    for (int t = 0; t < NTILES; t++) {
        if (t + 1 < NTILES) { asm volatile("cp.async.wait_group 1;" ::: "memory"); }
        else                { asm volatile("cp.async.wait_group 0;" ::: "memory"); }
        __syncthreads();

        const float* sk  = s_k + (t & 1) * NTILE * PAD;
        const float* svv = s_v + (t & 1) * NTILE;

        unsigned long long acc[4][4];
        #pragma unroll
        for (int i = 0; i < 4; i++)
            #pragma unroll
            for (int j = 0; j < 4; j++) acc[i][j] = 0ull;

        #pragma unroll 4
        for (int k = 0; k < KD; k += 4) {
            ulonglong2 av[4], bv[4];
            #pragma unroll
            for (int i = 0; i < 4; i++)
                av[i] = *(const ulonglong2*)(s_h + (mt + 16 * i) * PAD + k);
            #pragma unroll
            for (int j = 0; j < 4; j++)
                bv[j] = *(const ulonglong2*)(sk + (nt + 16 * j) * PAD + k);
            #pragma unroll
            for (int i = 0; i < 4; i++)
                #pragma unroll
                for (int j = 0; j < 4; j++) {
                    ffma2(acc[i][j], av[i].x, bv[j].x);
                    ffma2(acc[i][j], av[i].y, bv[j].y);
                }
        }

        float sv4[4];
        #pragma unroll
        for (int j = 0; j < 4; j++) sv4[j] = svv[nt + 16 * j];

        #pragma unroll
        for (int i = 0; i < 4; i++) {
            float s[4];
            #pragma unroll
            for (int j = 0; j < 4; j++) {
                float lo = __uint_as_float((unsigned)(acc[i][j] & 0xffffffffull));
                float hi = __uint_as_float((unsigned)(acc[i][j] >> 32));
                s[j] = (lo + hi) * scale2;
            }
            float tmax = fmaxf(fmaxf(s[0], s[1]), fmaxf(s[2], s[3]));
            if (tmax > rmax[i]) {
                float c = ex2(rmax[i] - tmax);
                rl[i] *= c; ra[i] *= c; rmax[i] = tmax;
            }
            #pragma unroll
            for (int j = 0; j < 4; j++) {
                float p = ex2(s[j] - rmax[i]);
                rl[i] += p;
                ra[i] = fmaf(p, sv4[j], ra[i]);
            }
        }

        __syncthreads();   // everyone done reading buf (t&1) before refill
        if (t + 2 < NTILES) {
            int tt = t + 2;
            #pragma unroll
            for (int j = 0; j < 8; j++) {
                int g  = j * 256 + tid;
                int n  = g >> 5;
                int k4 = g & 31;
                cp_async16(smem_u32(&s_k[(tt & 1) * NTILE * PAD + n * PAD + k4 * 4]),
                           keys + (size_t)(key0 + tt * NTILE + n) * 128 + k4 * 4);
            }
            if (tid < 16)
                cp_async16(smem_u32(&s_v[(tt & 1) * NTILE + tid * 4]),
                           values + key0 + tt * NTILE + tid * 4);
            cp_commit();
        }
    }

    // ---- merge across the 16 nt-threads sharing the same rows (half-warp xor) ----
    #pragma unroll
    for (int i = 0; i < 4; i++) {
        float m = rmax[i], l = rl[i], a = ra[i];
        #pragma unroll
        for (int d = 1; d < 16; d <<= 1) {
            float om = __shfl_xor_sync(0xffffffffu, m, d);
            float ol = __shfl_xor_sync(0xffffffffu, l, d);
            float oa = __shfl_xor_sync(0xffffffffu, a, d);
            float nm = fmaxf(m, om);
            float e1 = ex2(m - nm), e2 = ex2(om - nm);
            l = l * e1 + ol * e2;
            a = a * e1 + oa * e2;
            m = nm;
        }
        if (nt == 0) {
            int row = rb + mt + 16 * i;
            g_pm[row * KSPLIT + bx] = m;
            g_pl[row * KSPLIT + bx] = l;
            g_pa[row * KSPLIT + bx] = a;
        }
    }
}

// =====================================================================
// Combine: LSE-merge the KSPLIT partials per row. One warp per row.
// =====================================================================
__global__ void __launch_bounds__(256)
combine_kernel(float* __restrict__ out)
{
    const int tid  = threadIdx.x;
    const int w    = tid >> 5, lane = tid & 31;
    const int row  = blockIdx.x * 8 + w;
    const int base = row * KSPLIT;

    float m1 = g_pm[base + lane],      l1 = g_pl[base + lane],      a1 = g_pa[base + lane];
    float m2 = g_pm[base + lane + 32], l2 = g_pl[base + lane + 32], a2 = g_pa[base + lane + 32];

    float m = fmaxf(m1, m2);
    float e1 = ex2(m1 - m), e2 = ex2(m2 - m);
    float l = l1 * e1 + l2 * e2;
    float a = a1 * e1 + a2 * e2;

    #pragma unroll
    for (int d = 1; d < 32; d <<= 1) {
        float om = __shfl_xor_sync(0xffffffffu, m, d);
        float ol = __shfl_xor_sync(0xffffffffu, l, d);
        float oa = __shfl_xor_sync(0xffffffffu, a, d);
        float nm = fmaxf(m, om);
        float f1 = ex2(m - nm), f2 = ex2(om - nm);
        l = l * f1 + ol * f2;
        a = a * f1 + oa * f2;
        m = nm;
    }
    if (lane == 0) out[row] = a / l;
}

// =====================================================================
extern "C" void kernel_launch(void* const* d_in, const int* in_sizes, int n_in,
                              void* d_out, int out_size)
{
    const float* obs    = (const float*)d_in[0];
    const float* action = (const float*)d_in[1];
    const float* pW     = (const float*)d_in[2];
    const float* pb     = (const float*)d_in[3];
    const float* t1W    = (const float*)d_in[4];
    const float* t1b    = (const float*)d_in[5];
    const float* t2W    = (const float*)d_in[6];
    const float* t2b    = (const float*)d_in[7];
    const float* keys   = (const float*)d_in[8];
    const float* values = (const float*)d_in[9];
    const float* ltemp  = (const float*)d_in[10];
    float* out = (float*)d_out;

    const int smemB = (MTILE * PAD + 2 * NTILE * PAD + 2 * NTILE) * (int)sizeof(float); // 101888
    cudaFuncSetAttribute(phaseB_kernel, cudaFuncAttributeMaxDynamicSharedMemorySize, smemB);

    phaseA_kernel<<<B_ROWS / 8, 256>>>(obs, action, pW, pb, t1W, t1b, t2W, t2b);
    phaseB_kernel<<<dim3(KSPLIT, B_ROWS / MTILE), 256, smemB>>>(keys, values, ltemp);
    combine_kernel<<<B_ROWS / 8, 256>>>(out);
}

// round 4
// speedup vs baseline: 2.7080x; 2.7080x over previous
#include <cuda_runtime.h>
#include <cuda_bf16.h>
#include <math.h>

// ---------------- Problem constants ----------------
#define B_ROWS   1024
#define OBS_DIM  512
#define ACT_DIM  64
#define KD       128
#define CAP      131072

// ---------------- Phase B config ----------------
#define TILE_K   128                    // keys per tile
#define NKTILES  (CAP / TILE_K)         // 1024
#define NSPLIT   18                     // 8*18 = 144 CTAs ~ 1 wave
#define NPART    (NSPLIT * 2)           // 36 partials per row
#define PSTRIDE  40

// smem offsets (bytes, from dynamic smem base)
#define OFF_AHI  0
#define OFF_ALO  32768
#define OFF_B    65536                  // + stage*65536; lo at +32768
#define OFF_VAL  196608                 // 2 stages * 512B
#define SMEM_REQ 197632

// ---------------- Device scratch (no cudaMalloc allowed) ----------------
__device__ float g_H  [B_ROWS * KD];
__device__ uint4 g_khi[NKTILES * 2048];     // 32 MB swizzled bf16-hi key images
__device__ uint4 g_klo[NKTILES * 2048];     // 32 MB swizzled bf16-lo key images
__device__ uint4 g_ahi[8 * 2048];           // swizzled bf16-hi h images
__device__ uint4 g_alo[8 * 2048];
__device__ float g_pm [B_ROWS * PSTRIDE];
__device__ float g_pl [B_ROWS * PSTRIDE];
__device__ float g_pa [B_ROWS * PSTRIDE];

// ---------------- Helpers ----------------
__device__ __forceinline__ float ex2(float x) {
    float r; asm("ex2.approx.ftz.f32 %0, %1;" : "=f"(r) : "f"(x)); return r;
}
__device__ __forceinline__ unsigned smem_u32(const void* p) {
    return (unsigned)__cvta_generic_to_shared((void*)p);
}
__device__ __forceinline__ void cp_async16(unsigned dst, const void* src) {
    asm volatile("cp.async.cg.shared.global [%0], [%1], 16;" :: "r"(dst), "l"(src) : "memory");
}
__device__ __forceinline__ void cp_commit() {
    asm volatile("cp.async.commit_group;" ::: "memory");
}

// ldmatrix x4 (four 8x8 b16 matrices)
__device__ __forceinline__ void ldsm4(unsigned* r, unsigned addr) {
    asm volatile("ldmatrix.sync.aligned.m8n8.x4.shared.b16 {%0,%1,%2,%3}, [%4];"
                 : "=r"(r[0]), "=r"(r[1]), "=r"(r[2]), "=r"(r[3]) : "r"(addr));
}
// bf16 tensor-core MMA, fp32 accumulate
__device__ __forceinline__ void mma_bf16(float* c, const unsigned* a, const unsigned* b) {
    asm volatile("mma.sync.aligned.m16n8k16.row.col.f32.bf16.bf16.f32 "
                 "{%0,%1,%2,%3}, {%4,%5,%6,%7}, {%8,%9}, {%0,%1,%2,%3};"
                 : "+f"(c[0]), "+f"(c[1]), "+f"(c[2]), "+f"(c[3])
                 : "r"(a[0]), "r"(a[1]), "r"(a[2]), "r"(a[3]), "r"(b[0]), "r"(b[1]));
}

// Swizzled tile-image uint4 index for a 128x128 bf16 tile:
// row r (0..127), col chunk cc = k>>3 (0..15); chunk stored at cc ^ (r&7).
__device__ __forceinline__ unsigned img_idx(int r, int k) {
    unsigned cc = (unsigned)(k >> 3);
    return ((unsigned)r << 4) + (cc ^ ((unsigned)r & 7u));
}
// smem byte offset for (row, chunk cc)
__device__ __forceinline__ unsigned sw_off(unsigned r, unsigned cc) {
    return (r << 8) + ((cc ^ (r & 7u)) << 4);
}

// split 8 consecutive fp32 into packed bf16 hi / lo 16-byte chunks
__device__ __forceinline__ void split8(const float* x, uint4& hi, uint4& lo) {
    unsigned h[4], l[4];
    #pragma unroll
    for (int p = 0; p < 4; p++) {
        float a = x[2 * p], b = x[2 * p + 1];
        __nv_bfloat162 hh = __floats2bfloat162_rn(a, b);
        float ar = a - __bfloat162float(__low2bfloat16(hh));
        float br = b - __bfloat162float(__high2bfloat16(hh));
        __nv_bfloat162 ll = __floats2bfloat162_rn(ar, br);
        h[p] = *reinterpret_cast<unsigned*>(&hh);
        l[p] = *reinterpret_cast<unsigned*>(&ll);
    }
    hi = make_uint4(h[0], h[1], h[2], h[3]);
    lo = make_uint4(l[0], l[1], l[2], l[3]);
}

// =====================================================================
// Phase A: fused MLP. 4 rows per block, 256 threads, grid 256.
// =====================================================================
__global__ void __launch_bounds__(256)
phaseA_kernel(const float* __restrict__ obs,   const float* __restrict__ action,
              const float* __restrict__ pW,    const float* __restrict__ pb,
              const float* __restrict__ t1W,   const float* __restrict__ t1b,
              const float* __restrict__ t2W,   const float* __restrict__ t2b)
{
    __shared__ float s_obs[4 * 516];
    __shared__ float s_in [4 * 196];
    __shared__ float s_h1 [4 * 132];
    __shared__ float s_rn [4];

    const int tid = threadIdx.x;
    const int rb  = blockIdx.x * 4;

    #pragma unroll
    for (int j = 0; j < 2; j++) {          // 4 rows * 128 float4 = 512
        int g  = j * 256 + tid;
        int r  = g >> 7, k4 = g & 127;
        float4 v = ((const float4*)obs)[(rb + r) * 128 + k4];
        *(float4*)&s_obs[r * 516 + k4 * 4] = v;
    }
    {
        int r = tid >> 6, a = tid & 63;
        s_in[r * 196 + 128 + a] = action[(rb + r) * 64 + a];
    }
    __syncthreads();

    const int jj = tid & 127;
    const int rg = tid >> 7;

    float acc0[2] = {0.f, 0.f};
    {
        const float4* wp = (const float4*)pW + jj * 128;
        #pragma unroll 4
        for (int k = 0; k < 512; k += 4) {
            float4 w = __ldg(wp + (k >> 2));
            #pragma unroll
            for (int i = 0; i < 2; i++) {
                float4 o = *(const float4*)&s_obs[(rg * 2 + i) * 516 + k];
                acc0[i] = fmaf(w.x, o.x, acc0[i]);
                acc0[i] = fmaf(w.y, o.y, acc0[i]);
                acc0[i] = fmaf(w.z, o.z, acc0[i]);
                acc0[i] = fmaf(w.w, o.w, acc0[i]);
            }
        }
    }
    float bias0 = pb[jj];
    float raw[2];
    #pragma unroll
    for (int i = 0; i < 2; i++) {
        raw[i] = acc0[i] + bias0;
        s_in[(rg * 2 + i) * 196 + jj] = raw[i];
    }
    __syncthreads();

    {
        int w = tid >> 5, lane = tid & 31;
        if (w < 4) {
            float ss = 0.f;
            #pragma unroll
            for (int c = lane; c < 128; c += 32) {
                float x = s_in[w * 196 + c];
                ss = fmaf(x, x, ss);
            }
            #pragma unroll
            for (int d = 16; d > 0; d >>= 1) ss += __shfl_xor_sync(0xffffffffu, ss, d);
            if (lane == 0) s_rn[w] = 1.0f / fmaxf(sqrtf(ss), 1e-12f);
        }
    }
    __syncthreads();
    #pragma unroll
    for (int i = 0; i < 2; i++)
        s_in[(rg * 2 + i) * 196 + jj] = raw[i] * s_rn[rg * 2 + i];
    __syncthreads();

    float acc1[2] = {0.f, 0.f};
    {
        const float4* wp = (const float4*)t1W + jj * 48;
        #pragma unroll 4
        for (int k = 0; k < 192; k += 4) {
            float4 w = __ldg(wp + (k >> 2));
            #pragma unroll
            for (int i = 0; i < 2; i++) {
                float4 o = *(const float4*)&s_in[(rg * 2 + i) * 196 + k];
                acc1[i] = fmaf(w.x, o.x, acc1[i]);
                acc1[i] = fmaf(w.y, o.y, acc1[i]);
                acc1[i] = fmaf(w.z, o.z, acc1[i]);
                acc1[i] = fmaf(w.w, o.w, acc1[i]);
            }
        }
    }
    float bias1 = t1b[jj];
    #pragma unroll
    for (int i = 0; i < 2; i++)
        s_h1[(rg * 2 + i) * 132 + jj] = fmaxf(acc1[i] + bias1, 0.0f);
    __syncthreads();

    float acc2[2] = {0.f, 0.f};
    {
        const float4* wp = (const float4*)t2W + jj * 32;
        #pragma unroll 4
        for (int k = 0; k < 128; k += 4) {
            float4 w = __ldg(wp + (k >> 2));
            #pragma unroll
            for (int i = 0; i < 2; i++) {
                float4 o = *(const float4*)&s_h1[(rg * 2 + i) * 132 + k];
                acc2[i] = fmaf(w.x, o.x, acc2[i]);
                acc2[i] = fmaf(w.y, o.y, acc2[i]);
                acc2[i] = fmaf(w.z, o.z, acc2[i]);
                acc2[i] = fmaf(w.w, o.w, acc2[i]);
            }
        }
    }
    float bias2 = t2b[jj];
    #pragma unroll
    for (int i = 0; i < 2; i++)
        g_H[(rb + rg * 2 + i) * 128 + jj] = acc2[i] + bias2;
}

// =====================================================================
// convert_h: g_H -> swizzled bf16 hi/lo A-tile images (8 m-blocks)
// =====================================================================
__global__ void __launch_bounds__(256)
convert_h_kernel()
{
    int id  = blockIdx.x * 256 + threadIdx.x;   // 0..16383
    int row = id >> 4;
    int kc  = (id & 15) * 8;
    float x[8];
    *(float4*)&x[0] = *(const float4*)&g_H[row * 128 + kc];
    *(float4*)&x[4] = *(const float4*)&g_H[row * 128 + kc + 4];
    uint4 hi, lo;
    split8(x, hi, lo);
    int mb = row >> 7, r = row & 127;
    unsigned off = img_idx(r, kc);
    g_ahi[mb * 2048 + off] = hi;
    g_alo[mb * 2048 + off] = lo;
}

// =====================================================================
// convert_keys: keys fp32 -> swizzled bf16 hi/lo key tile images
// =====================================================================
__global__ void __launch_bounds__(256)
convert_keys_kernel(const float* __restrict__ keys)
{
    int id  = blockIdx.x * 256 + threadIdx.x;   // 0..2097151
    int row = id >> 4;
    int kc  = (id & 15) * 8;
    float x[8];
    *(float4*)&x[0] = __ldg((const float4*)(keys + (size_t)row * 128 + kc));
    *(float4*)&x[4] = __ldg((const float4*)(keys + (size_t)row * 128 + kc + 4));
    uint4 hi, lo;
    split8(x, hi, lo);
    int tile = row >> 7, r = row & 127;
    unsigned off = img_idx(r, kc);
    g_khi[tile * 2048 + off] = hi;
    g_klo[tile * 2048 + off] = lo;
}

// =====================================================================
// Phase B: mma.sync (HMMA) flash-decode. Grid (8 mblocks, 18 splits),
// 256 threads = 8 warps: wm = wid&3 (32 rows), wn = wid>>2 (64 keys).
// Per tile: 3-term bf16 hi/lo MMA into fp32 register accumulators,
// register-resident online softmax, cp.async double-buffered key tiles.
// =====================================================================
__global__ void __launch_bounds__(256, 1)
phaseB_mma(const float* __restrict__ values, const float* __restrict__ log_temp)
{
    extern __shared__ __align__(16) unsigned char smg[];
    const unsigned sb = smem_u32(smg);

    const int tid  = threadIdx.x;
    const int wid  = tid >> 5;
    const int lane = tid & 31;
    const int wm   = wid & 3;           // 4 m-warps, 32 rows each
    const int wn   = wid >> 2;          // 2 n-warps, 64 keys each
    const int mblock = blockIdx.x;
    const int split  = blockIdx.y;

    const int t0 = (split * NKTILES) / NSPLIT;
    const int t1 = ((split + 1) * NKTILES) / NSPLIT;
    const int nt = t1 - t0;

    const float L2E = 1.4426950408889634f;
    const float scale2 = ex2(-__ldg(log_temp) * L2E) * L2E;   // (1/T)*log2(e)

    // ---- prologue: A images + tile 0 (group 0), tile 1 (group 1) ----
    {
        const uint4* ah = g_ahi + mblock * 2048;
        const uint4* al = g_alo + mblock * 2048;
        #pragma unroll
        for (int it = 0; it < 8; it++) {
            int q = it * 256 + tid;
            cp_async16(sb + OFF_AHI + q * 16, ah + q);
            cp_async16(sb + OFF_ALO + q * 16, al + q);
        }
        const uint4* kh = g_khi + (size_t)t0 * 2048;
        const uint4* kl = g_klo + (size_t)t0 * 2048;
        #pragma unroll
        for (int it = 0; it < 8; it++) {
            int q = it * 256 + tid;
            cp_async16(sb + OFF_B + q * 16, kh + q);
            cp_async16(sb + OFF_B + 32768 + q * 16, kl + q);
        }
        if (tid < 32)
            cp_async16(sb + OFF_VAL + tid * 16, values + (size_t)t0 * 128 + tid * 4);
        cp_commit();
        if (nt > 1) {
            const uint4* kh1 = g_khi + (size_t)(t0 + 1) * 2048;
            const uint4* kl1 = g_klo + (size_t)(t0 + 1) * 2048;
            #pragma unroll
            for (int it = 0; it < 8; it++) {
                int q = it * 256 + tid;
                cp_async16(sb + OFF_B + 65536 + q * 16, kh1 + q);
                cp_async16(sb + OFF_B + 65536 + 32768 + q * 16, kl1 + q);
            }
            if (tid < 32)
                cp_async16(sb + OFF_VAL + 512 + tid * 16,
                           values + (size_t)(t0 + 1) * 128 + tid * 4);
            cp_commit();
        }
    }

    // per-lane ldmatrix sub-assignments
    const unsigned rr = lane & 7;
    const unsigned s  = lane >> 3;       // submatrix id 0..3
    // A: rowhalf = s&1, khalf = s>>1 ; B: keyhalf = s>>1, khalf = s&1
    const unsigned a_r0 = (unsigned)(wm * 32) + (s & 1) * 8 + rr;
    const unsigned b_r0 = (unsigned)(wn * 64) + (s >> 1) * 8 + rr;
    const unsigned a_cc0 = (s >> 1);
    const unsigned b_cc0 = (s & 1);

    // online-softmax state: 4 row-slots (mt*2 + h), row = wm*32+mt*16+h*8+(lane>>2)
    float sm_[4], sl_[4], sa_[4];
    #pragma unroll
    for (int i = 0; i < 4; i++) { sm_[i] = -1e30f; sl_[i] = 0.f; sa_[i] = 0.f; }

    for (int rel = 0; rel < nt; rel++) {
        if (rel + 1 < nt) { asm volatile("cp.async.wait_group 1;" ::: "memory"); }
        else              { asm volatile("cp.async.wait_group 0;" ::: "memory"); }
        __syncthreads();

        const unsigned bhi_base = sb + OFF_B + (rel & 1) * 65536;
        const unsigned blo_base = bhi_base + 32768;

        float acc[2][8][4];
        #pragma unroll
        for (int mt = 0; mt < 2; mt++)
            #pragma unroll
            for (int j = 0; j < 8; j++)
                #pragma unroll
                for (int q = 0; q < 4; q++) acc[mt][j][q] = 0.f;

        #pragma unroll
        for (int kc = 0; kc < 8; kc++) {
            unsigned ahi[2][4], alo[2][4], bhi[4][4], blo[4][4];
            #pragma unroll
            for (int mt = 0; mt < 2; mt++) {
                unsigned off = sw_off(a_r0 + mt * 16, (unsigned)kc * 2 + a_cc0);
                ldsm4(ahi[mt], sb + OFF_AHI + off);
                ldsm4(alo[mt], sb + OFF_ALO + off);
            }
            #pragma unroll
            for (int p = 0; p < 4; p++) {
                unsigned off = sw_off(b_r0 + p * 16, (unsigned)kc * 2 + b_cc0);
                ldsm4(bhi[p], bhi_base + off);
                ldsm4(blo[p], blo_base + off);
            }
            #pragma unroll
            for (int mt = 0; mt < 2; mt++)
                #pragma unroll
                for (int j = 0; j < 8; j++) {
                    const int p = j >> 1, q = (j & 1) * 2;
                    mma_bf16(acc[mt][j], ahi[mt], &bhi[p][q]);
                    mma_bf16(acc[mt][j], ahi[mt], &blo[p][q]);
                    mma_bf16(acc[mt][j], alo[mt], &bhi[p][q]);
                }
        }

        // ---- epilogue: online softmax on register accumulators ----
        {
            const float* sv = (const float*)(smg + OFF_VAL + (rel & 1) * 512) + wn * 64;
            float vv[16];
            #pragma unroll
            for (int j = 0; j < 8; j++) {
                float2 v2 = *(const float2*)(sv + j * 8 + 2 * (lane & 3));
                vv[j * 2]     = v2.x;
                vv[j * 2 + 1] = v2.y;
            }
            #pragma unroll
            for (int mt = 0; mt < 2; mt++)
                #pragma unroll
                for (int h = 0; h < 2; h++) {
                    const int slot = mt * 2 + h;
                    float sarr[16];
                    #pragma unroll
                    for (int j = 0; j < 8; j++) {
                        sarr[j * 2]     = acc[mt][j][h * 2]     * scale2;
                        sarr[j * 2 + 1] = acc[mt][j][h * 2 + 1] * scale2;
                    }
                    float tm = sarr[0];
                    #pragma unroll
                    for (int c = 1; c < 16; c++) tm = fmaxf(tm, sarr[c]);
                    if (tm > sm_[slot]) {
                        float cr = ex2(sm_[slot] - tm);
                        sl_[slot] *= cr; sa_[slot] *= cr; sm_[slot] = tm;
                    }
                    float lacc = 0.f, aacc = 0.f;
                    #pragma unroll
                    for (int c = 0; c < 16; c++) {
                        float p = ex2(sarr[c] - sm_[slot]);
                        lacc += p;
                        aacc = fmaf(p, vv[c], aacc);
                    }
                    sl_[slot] += lacc;
                    sa_[slot] += aacc;
                }
        }

        __syncthreads();   // all warps done reading buffer (rel&1)
        if (rel + 2 < nt) {
            int gt = t0 + rel + 2;
            const uint4* kh = g_khi + (size_t)gt * 2048;
            const uint4* kl = g_klo + (size_t)gt * 2048;
            unsigned bbase = sb + OFF_B + (rel & 1) * 65536;
            #pragma unroll
            for (int it = 0; it < 8; it++) {
                int q = it * 256 + tid;
                cp_async16(bbase + q * 16, kh + q);
                cp_async16(bbase + 32768 + q * 16, kl + q);
            }
            if (tid < 32)
                cp_async16(sb + OFF_VAL + (rel & 1) * 512 + tid * 16,
                           values + (size_t)gt * 128 + tid * 4);
            cp_commit();
        }
    }

    // ---- merge across the 4 lanes sharing each row; write partials ----
    #pragma unroll
    for (int slot = 0; slot < 4; slot++) {
        float m = sm_[slot], l = sl_[slot], a = sa_[slot];
        #pragma unroll
        for (int d = 1; d < 4; d <<= 1) {
            float om = __shfl_xor_sync(0xffffffffu, m, d);
            float ol = __shfl_xor_sync(0xffffffffu, l, d);
            float oa = __shfl_xor_sync(0xffffffffu, a, d);
            float nm = fmaxf(m, om);
            float e1 = ex2(m - nm), e2 = ex2(om - nm);
            l = l * e1 + ol * e2;
            a = a * e1 + oa * e2;
            m = nm;
        }
        if ((lane & 3) == 0) {
            int mt = slot >> 1, h = slot & 1;
            int row  = mblock * 128 + wm * 32 + mt * 16 + h * 8 + (lane >> 2);
            int pidx = split * 2 + wn;
            g_pm[row * PSTRIDE + pidx] = m;
            g_pl[row * PSTRIDE + pidx] = l;
            g_pa[row * PSTRIDE + pidx] = a;
        }
    }
}

// =====================================================================
// Combine: LSE-merge NPART partials per row. One warp per row.
// =====================================================================
__global__ void __launch_bounds__(256)
combine_kernel(float* __restrict__ out)
{
    const int tid  = threadIdx.x;
    const int w    = tid >> 5, lane = tid & 31;
    const int row  = blockIdx.x * 8 + w;
    const int base = row * PSTRIDE;

    float m = -1e30f, l = 0.f, a = 0.f;
    if (lane < NPART) { m = g_pm[base + lane]; l = g_pl[base + lane]; a = g_pa[base + lane]; }
    if (lane + 32 < NPART) {
        float m2 = g_pm[base + lane + 32], l2 = g_pl[base + lane + 32], a2 = g_pa[base + lane + 32];
        float nm = fmaxf(m, m2);
        float e1 = ex2(m - nm), e2 = ex2(m2 - nm);
        l = l * e1 + l2 * e2;
        a = a * e1 + a2 * e2;
        m = nm;
    }
    #pragma unroll
    for (int d = 1; d < 32; d <<= 1) {
        float om = __shfl_xor_sync(0xffffffffu, m, d);
        float ol = __shfl_xor_sync(0xffffffffu, l, d);
        float oa = __shfl_xor_sync(0xffffffffu, a, d);
        float nm = fmaxf(m, om);
        float f1 = ex2(m - nm), f2 = ex2(om - nm);
        l = l * f1 + ol * f2;
        a = a * f1 + oa * f2;
        m = nm;
    }
    if (lane == 0) out[row] = a / l;
}

// =====================================================================
extern "C" void kernel_launch(void* const* d_in, const int* in_sizes, int n_in,
                              void* d_out, int out_size)
{
    const float* obs    = (const float*)d_in[0];
    const float* action = (const float*)d_in[1];
    const float* pW     = (const float*)d_in[2];
    const float* pb     = (const float*)d_in[3];
    const float* t1W    = (const float*)d_in[4];
    const float* t1b    = (const float*)d_in[5];
    const float* t2W    = (const float*)d_in[6];
    const float* t2b    = (const float*)d_in[7];
    const float* keys   = (const float*)d_in[8];
    const float* values = (const float*)d_in[9];
    const float* ltemp  = (const float*)d_in[10];
    float* out = (float*)d_out;

    cudaFuncSetAttribute(phaseB_mma, cudaFuncAttributeMaxDynamicSharedMemorySize, SMEM_REQ);

    phaseA_kernel<<<B_ROWS / 4, 256>>>(obs, action, pW, pb, t1W, t1b, t2W, t2b);
    convert_h_kernel<<<64, 256>>>();
    convert_keys_kernel<<<CAP / 16, 256>>>(keys);
    phaseB_mma<<<dim3(8, NSPLIT), 256, SMEM_REQ>>>(values, ltemp);
    combine_kernel<<<B_ROWS / 8, 256>>>(out);
}